// round 13
// baseline (speedup 1.0000x reference)
#include <cuda_runtime.h>
#include <cuda_fp16.h>
#include <math.h>

#define BB 2
#define TT 2048
#define CC 1024
#define HH 16
#define HD 64

// Scratch (allocation-free rule: __device__ globals). fp16.
__device__ __half g_xt[4096*1024];     // x converted
__device__ __half g_wt[3072*1024];     // [Wq;Wk;Wv] converted
__device__ __half g_wpt[1024*1024];    // Wp converted
__device__ __half g_q[BB*HH*TT*HD];
__device__ __half g_k[BB*HH*TT*HD];
__device__ __half g_v[BB*HH*TT*HD];
__device__ __half g_y[BB*TT*CC];

// ---------------------------------------------------------------------------
// helpers
// ---------------------------------------------------------------------------
__device__ __forceinline__ void mma16(float* c, const unsigned* a, const unsigned* b) {
    asm volatile(
        "mma.sync.aligned.m16n8k16.row.col.f32.f16.f16.f32 "
        "{%0,%1,%2,%3},{%4,%5,%6,%7},{%8,%9},{%0,%1,%2,%3};"
        : "+f"(c[0]), "+f"(c[1]), "+f"(c[2]), "+f"(c[3])
        : "r"(a[0]), "r"(a[1]), "r"(a[2]), "r"(a[3]), "r"(b[0]), "r"(b[1]));
}

__device__ __forceinline__ void ldsm4(unsigned& d0, unsigned& d1, unsigned& d2,
                                      unsigned& d3, unsigned addr) {
    asm volatile("ldmatrix.sync.aligned.m8n8.x4.shared.b16 {%0,%1,%2,%3}, [%4];"
                 : "=r"(d0), "=r"(d1), "=r"(d2), "=r"(d3) : "r"(addr));
}
__device__ __forceinline__ void ldsm4t(unsigned& d0, unsigned& d1, unsigned& d2,
                                       unsigned& d3, unsigned addr) {
    asm volatile("ldmatrix.sync.aligned.m8n8.x4.trans.shared.b16 {%0,%1,%2,%3}, [%4];"
                 : "=r"(d0), "=r"(d1), "=r"(d2), "=r"(d3) : "r"(addr));
}

__device__ __forceinline__ void cp16(void* dst_smem, const void* src) {
    unsigned d = (unsigned)__cvta_generic_to_shared(dst_smem);
    asm volatile("cp.async.cg.shared.global [%0], [%1], 16;\n" :: "r"(d), "l"(src));
}
__device__ __forceinline__ void cp_commit() {
    asm volatile("cp.async.commit_group;\n");
}
__device__ __forceinline__ void cp_wait0() {
    asm volatile("cp.async.wait_group 0;\n");
}

// ---------------------------------------------------------------------------
// Pre-convert x and weights to fp16.
// ---------------------------------------------------------------------------
__global__ __launch_bounds__(256) void convert_fp16(
    const float* __restrict__ x,
    const float* __restrict__ Wq, const float* __restrict__ Wk,
    const float* __restrict__ Wv, const float* __restrict__ Wp)
{
    int i = blockIdx.x * 256 + threadIdx.x;   // float4 index
    if (i >= 2097152) return;
    const float* src; __half* dst; int off;
    if (i < 1048576)      { src = x;  dst = g_xt;            off = i; }
    else if (i < 1310720) { src = Wq; dst = g_wt;            off = i - 1048576; }
    else if (i < 1572864) { src = Wk; dst = g_wt + 1048576;  off = i - 1310720; }
    else if (i < 1835008) { src = Wv; dst = g_wt + 2097152;  off = i - 1572864; }
    else                  { src = Wp; dst = g_wpt;           off = i - 1835008; }
    float4 v = ((const float4*)src)[off];
    __half2 lo = __floats2half2_rn(v.x, v.y);
    __half2 hi = __floats2half2_rn(v.z, v.w);
    uint2 o;
    o.x = *(unsigned*)&lo;
    o.y = *(unsigned*)&hi;
    ((uint2*)dst)[off] = o;
}

// ---------------------------------------------------------------------------
// GEMM core: 128x128 tile, BK=64 (halfs), 2-stage cp.async double buffer.
// 8 warps (2m x 4n), warp tile 64x32. m16n8k16 fp16 mma, ldmatrix loads.
// Smem halfs, row stride 72 (144B -> conflict-free ldmatrix).
//   A: stages at byte 0 and 18432;  B: 36864 + stage*18432. Total 73728 B.
// ---------------------------------------------------------------------------
struct GemmAcc { float a[4][4][4]; };

__device__ __forceinline__ void gemm_core(
    __half* smh, const __half* Ag, const __half* Bg, GemmAcc& acc)
{
    int tid = threadIdx.x;
    int lane = tid & 31, warp = tid >> 5;
    int wm = warp >> 2, wn = warp & 3;

    #pragma unroll
    for (int mt = 0; mt < 4; mt++)
        #pragma unroll
        for (int nt = 0; nt < 4; nt++)
            #pragma unroll
            for (int i = 0; i < 4; i++) acc.a[mt][nt][i] = 0.f;

    unsigned sbase = (unsigned)__cvta_generic_to_shared(smh);

    unsigned a_off[4];
    #pragma unroll
    for (int mt = 0; mt < 4; mt++)
        a_off[mt] = (unsigned)((wm * 64 + mt * 16 + (lane & 15)) * 144
                               + (lane >> 4) * 16);
    unsigned b_off[2];
    #pragma unroll
    for (int np = 0; np < 2; np++) {
        int row = wn * 32 + np * 16 + ((lane >> 4) * 8) + (lane & 7);
        b_off[np] = (unsigned)(36864 + row * 144 + ((lane >> 3) & 1) * 16);
    }

    #pragma unroll
    for (int i = 0; i < 4; i++) {
        int linear = tid + i * 256;
        int row = linear >> 3, c16 = linear & 7;
        cp16(smh + row * 72 + c16 * 8, Ag + (size_t)row * CC + c16 * 8);
        cp16(smh + 18432 + row * 72 + c16 * 8, Bg + (size_t)row * CC + c16 * 8);
    }
    cp_commit();

    int buf = 0;
    for (int it = 0; it < 16; it++) {
        cp_wait0();
        __syncthreads();
        if (it < 15) {
            int k0 = (it + 1) * 64;
            int so = (buf ^ 1) * 9216;   // stage offset in halfs
            #pragma unroll
            for (int i = 0; i < 4; i++) {
                int linear = tid + i * 256;
                int row = linear >> 3, c16 = linear & 7;
                cp16(smh + so + row * 72 + c16 * 8,
                     Ag + (size_t)row * CC + k0 + c16 * 8);
                cp16(smh + 18432 + so + row * 72 + c16 * 8,
                     Bg + (size_t)row * CC + k0 + c16 * 8);
            }
            cp_commit();
        }

        unsigned stage_b = buf * 18432;   // bytes
        #pragma unroll
        for (int kk = 0; kk < 4; kk++) {
            unsigned kbb = stage_b + kk * 32;
            unsigned a[4][4], b[4][2];
            #pragma unroll
            for (int mt = 0; mt < 4; mt++)
                ldsm4(a[mt][0], a[mt][1], a[mt][2], a[mt][3],
                      sbase + a_off[mt] + kbb);
            #pragma unroll
            for (int np = 0; np < 2; np++)
                ldsm4(b[2*np][0], b[2*np][1], b[2*np+1][0], b[2*np+1][1],
                      sbase + b_off[np] + kbb);
            #pragma unroll
            for (int mt = 0; mt < 4; mt++)
                #pragma unroll
                for (int nt = 0; nt < 4; nt++)
                    mma16(acc.a[mt][nt], a[mt], b[nt]);
        }
        buf ^= 1;
    }
}

// ---------------------------------------------------------------------------
// QKV projection -> fp16 in [B,H,T,HD]
// ---------------------------------------------------------------------------
__global__ __launch_bounds__(256) void qkv_gemm6(
    const float* __restrict__ bq, const float* __restrict__ bk,
    const float* __restrict__ bv)
{
    extern __shared__ __half smh[];
    int tid = threadIdx.x;
    int lane = tid & 31, warp = tid >> 5;
    int g = lane >> 2, t4 = lane & 3;
    int wm = warp >> 2, wn = warp & 3;

    int mbase = blockIdx.y * 128;
    int cb = blockIdx.x * 128;
    int mat = cb >> 10;
    int nloc = cb & 1023;

    const float* bias = (mat == 0) ? bq : (mat == 1) ? bk : bv;
    __half* out       = (mat == 0) ? g_q : (mat == 1) ? g_k : g_v;

    GemmAcc acc;
    gemm_core(smh, g_xt + (size_t)mbase * CC, g_wt + (size_t)cb * CC, acc);

    #pragma unroll
    for (int mt = 0; mt < 4; mt++) {
        int m0 = mbase + wm * 64 + mt * 16 + g;
        #pragma unroll
        for (int nt = 0; nt < 4; nt++) {
            int n0 = nloc + wn * 32 + nt * 8 + 2 * t4;
            int hh = n0 >> 6, d0 = n0 & 63;
            float bx = bias[n0], by = bias[n0 + 1];
            #pragma unroll
            for (int rr = 0; rr < 2; rr++) {
                int m = m0 + rr * 8;
                int bidx = m >> 11, t = m & (TT - 1);
                __half2 v = __floats2half2_rn(acc.a[mt][nt][rr * 2 + 0] + bx,
                                              acc.a[mt][nt][rr * 2 + 1] + by);
                *(__half2*)&out[(((size_t)(bidx * HH + hh) * TT) + t) * HD + d0] = v;
            }
        }
    }
}

// ---------------------------------------------------------------------------
// Output projection -> f32 out
// ---------------------------------------------------------------------------
__global__ __launch_bounds__(256) void proj_gemm6(
    const float* __restrict__ bp, float* __restrict__ out)
{
    extern __shared__ __half smh[];
    int tid = threadIdx.x;
    int lane = tid & 31, warp = tid >> 5;
    int g = lane >> 2, t4 = lane & 3;
    int wm = warp >> 2, wn = warp & 3;

    int mbase = blockIdx.y * 128;
    int nbase = blockIdx.x * 128;

    GemmAcc acc;
    gemm_core(smh, g_y + (size_t)mbase * CC, g_wpt + (size_t)nbase * CC, acc);

    #pragma unroll
    for (int mt = 0; mt < 4; mt++) {
        int m0 = mbase + wm * 64 + mt * 16 + g;
        #pragma unroll
        for (int nt = 0; nt < 4; nt++) {
            int n0 = nbase + wn * 32 + nt * 8 + 2 * t4;
            float bx = bp[n0], by = bp[n0 + 1];
            #pragma unroll
            for (int rr = 0; rr < 2; rr++) {
                int m = m0 + rr * 8;
                float2 v;
                v.x = acc.a[mt][nt][rr * 2 + 0] + bx;
                v.y = acc.a[mt][nt][rr * 2 + 1] + by;
                *(float2*)&out[(size_t)m * CC + n0] = v;
            }
        }
    }
}

// ---------------------------------------------------------------------------
// Flash attention v2: 256 threads = 8 warps, q-tile 128 rows (warp w owns
// rows [qt*128+16w, +16)). K/V tiles of 64 rows shared by all 8 warps.
// P in its own per-warp smem region -> no mid-loop __syncthreads.
// Q pre-scaled by 0.125 (exact in fp16) at fragment load.
// ---------------------------------------------------------------------------
__global__ __launch_bounds__(256) void attn_tc6(const float* __restrict__ hbias)
{
    __shared__ __half Ks[64][72];
    __shared__ __half Vs[64][72];
    __shared__ __half Ps[128][72];

    int tid = threadIdx.x;
    int lane = tid & 31, warp = tid >> 5;
    int g = lane >> 2, t4 = lane & 3;

    int qt = (int)gridDim.x - 1 - (int)blockIdx.x;  // heavy tiles first
    int hh = blockIdx.y;
    int b  = blockIdx.z;
    int qbase = qt * 128;
    int qg0 = qbase + warp * 16 + g;
    int qg1 = qg0 + 8;

    const __half* qptr = g_q + (size_t)(b * HH + hh) * TT * HD;
    const __half* kptr = g_k + (size_t)(b * HH + hh) * TT * HD;
    const __half* vptr = g_v + (size_t)(b * HH + hh) * TT * HD;
    const float* hb0 = hbias + (size_t)(b * HH + hh) * TT * TT + (size_t)qg0 * TT;
    const float* hb1 = hb0 + (size_t)8 * TT;

    unsigned ks_base = (unsigned)__cvta_generic_to_shared(&Ks[0][0]);
    unsigned vs_base = (unsigned)__cvta_generic_to_shared(&Vs[0][0]);
    unsigned ps_base = (unsigned)__cvta_generic_to_shared(&Ps[0][0]);

    // ldmatrix offsets
    unsigned k_off[4];     // S-phase B: np covers nt pair
    #pragma unroll
    for (int np = 0; np < 4; np++) {
        int row = np * 16 + ((lane >> 4) * 8) + (lane & 7);
        k_off[np] = (unsigned)(row * 144 + ((lane >> 3) & 1) * 16);
    }
    unsigned p_off = (unsigned)((warp * 16 + (lane & 15)) * 144 + (lane >> 4) * 16);
    unsigned v_off[4];     // PV-phase B (trans): np covers d pair
    #pragma unroll
    for (int np = 0; np < 4; np++)
        v_off[np] = (unsigned)((lane & 15) * 144 + (np * 16 + (lane >> 4) * 8) * 2);

    // Q fragments, pre-scaled by 1/sqrt(HD) = 0.125 (exact in fp16)
    const __half2 qscale = __float2half2_rn(0.125f);
    unsigned qa[4][4];
    #pragma unroll
    for (int kk = 0; kk < 4; kk++) {
        int dc = kk * 16 + 2 * t4;
        unsigned u0 = *(const unsigned*)(qptr + (size_t)qg0 * HD + dc);
        unsigned u1 = *(const unsigned*)(qptr + (size_t)qg1 * HD + dc);
        unsigned u2 = *(const unsigned*)(qptr + (size_t)qg0 * HD + dc + 8);
        unsigned u3 = *(const unsigned*)(qptr + (size_t)qg1 * HD + dc + 8);
        __half2 h0 = __hmul2(*(__half2*)&u0, qscale);
        __half2 h1 = __hmul2(*(__half2*)&u1, qscale);
        __half2 h2 = __hmul2(*(__half2*)&u2, qscale);
        __half2 h3 = __hmul2(*(__half2*)&u3, qscale);
        qa[kk][0] = *(unsigned*)&h0;
        qa[kk][1] = *(unsigned*)&h1;
        qa[kk][2] = *(unsigned*)&h2;
        qa[kk][3] = *(unsigned*)&h3;
    }

    float m0 = -INFINITY, m1 = -INFINITY, l0 = 0.f, l1 = 0.f;
    float O[8][4];
    #pragma unroll
    for (int nt = 0; nt < 8; nt++)
        #pragma unroll
        for (int i = 0; i < 4; i++) O[nt][i] = 0.f;

    int ntiles = 2 * qt + 2;      // 64-row k tiles covering causal span
    for (int j = 0; j < ntiles; j++) {
        int kb = j * 64;
        __syncthreads();   // all warps done with previous Ks/Vs
        #pragma unroll
        for (int i = 0; i < 2; i++) {
            int idx = tid + i * 256;
            int row = idx >> 3, c16 = idx & 7;
            *(uint4*)&Ks[row][c16 * 8] =
                *(const uint4*)(kptr + (size_t)(kb + row) * HD + c16 * 8);
            *(uint4*)&Vs[row][c16 * 8] =
                *(const uint4*)(vptr + (size_t)(kb + row) * HD + c16 * 8);
        }
        __syncthreads();

        // prefetch h-bias into regs
        float2 hA[8], hB[8];
        #pragma unroll
        for (int nt = 0; nt < 8; nt++) {
            int kg = kb + nt * 8 + 2 * t4;
            hA[nt] = *(const float2*)&hb0[kg];
            hB[nt] = *(const float2*)&hb1[kg];
        }

        // S = (Q*0.125) K^T
        float s[8][4];
        #pragma unroll
        for (int nt = 0; nt < 8; nt++)
            s[nt][0] = s[nt][1] = s[nt][2] = s[nt][3] = 0.f;
        #pragma unroll
        for (int kk = 0; kk < 4; kk++) {
            unsigned bfr[8][2];
            #pragma unroll
            for (int np = 0; np < 4; np++)
                ldsm4(bfr[2*np][0], bfr[2*np][1], bfr[2*np+1][0], bfr[2*np+1][1],
                      ks_base + k_off[np] + kk * 32);
            #pragma unroll
            for (int nt = 0; nt < 8; nt++)
                mma16(s[nt], qa[kk], bfr[nt]);
        }

        // bias + causal mask + row max (no cross-warp hazard: P is private)
        float mt0 = -INFINITY, mt1 = -INFINITY;
        #pragma unroll
        for (int nt = 0; nt < 8; nt++) {
            int kg = kb + nt * 8 + 2 * t4;
            s[nt][0] = (kg     <= qg0) ? s[nt][0] + hA[nt].x : -INFINITY;
            s[nt][1] = (kg + 1 <= qg0) ? s[nt][1] + hA[nt].y : -INFINITY;
            s[nt][2] = (kg     <= qg1) ? s[nt][2] + hB[nt].x : -INFINITY;
            s[nt][3] = (kg + 1 <= qg1) ? s[nt][3] + hB[nt].y : -INFINITY;
            mt0 = fmaxf(mt0, fmaxf(s[nt][0], s[nt][1]));
            mt1 = fmaxf(mt1, fmaxf(s[nt][2], s[nt][3]));
        }
        mt0 = fmaxf(mt0, __shfl_xor_sync(0xffffffffu, mt0, 1));
        mt0 = fmaxf(mt0, __shfl_xor_sync(0xffffffffu, mt0, 2));
        mt1 = fmaxf(mt1, __shfl_xor_sync(0xffffffffu, mt1, 1));
        mt1 = fmaxf(mt1, __shfl_xor_sync(0xffffffffu, mt1, 2));

        float mn0 = fmaxf(m0, mt0), mn1 = fmaxf(m1, mt1);
        float al0 = __expf(m0 - mn0), al1 = __expf(m1 - mn1);
        float ls0 = 0.f, ls1 = 0.f;
        #pragma unroll
        for (int nt = 0; nt < 8; nt++) {
            s[nt][0] = __expf(s[nt][0] - mn0);
            s[nt][1] = __expf(s[nt][1] - mn0);
            s[nt][2] = __expf(s[nt][2] - mn1);
            s[nt][3] = __expf(s[nt][3] - mn1);
            ls0 += s[nt][0] + s[nt][1];
            ls1 += s[nt][2] + s[nt][3];
        }
        ls0 += __shfl_xor_sync(0xffffffffu, ls0, 1);
        ls0 += __shfl_xor_sync(0xffffffffu, ls0, 2);
        ls1 += __shfl_xor_sync(0xffffffffu, ls1, 1);
        ls1 += __shfl_xor_sync(0xffffffffu, ls1, 2);
        l0 = l0 * al0 + ls0;  m0 = mn0;
        l1 = l1 * al1 + ls1;  m1 = mn1;
        #pragma unroll
        for (int nt = 0; nt < 8; nt++) {
            O[nt][0] *= al0; O[nt][1] *= al0;
            O[nt][2] *= al1; O[nt][3] *= al1;
        }

        // P (fp16) into own-warp Ps rows
        int pr0 = warp * 16 + g;
        #pragma unroll
        for (int nt = 0; nt < 8; nt++) {
            int c = nt * 8 + 2 * t4;
            *(__half2*)&Ps[pr0][c]     = __floats2half2_rn(s[nt][0], s[nt][1]);
            *(__half2*)&Ps[pr0 + 8][c] = __floats2half2_rn(s[nt][2], s[nt][3]);
        }
        __syncwarp();

        // O += P V   (A = P via ldmatrix, B = V^T via ldmatrix.trans)
        #pragma unroll
        for (int kk = 0; kk < 4; kk++) {
            unsigned ap[4];
            ldsm4(ap[0], ap[1], ap[2], ap[3], ps_base + p_off + kk * 32);
            unsigned bv_[8][2];
            #pragma unroll
            for (int np = 0; np < 4; np++)
                ldsm4t(bv_[2*np][0], bv_[2*np][1], bv_[2*np+1][0], bv_[2*np+1][1],
                       vs_base + v_off[np] + kk * 2304);
            #pragma unroll
            for (int nt = 0; nt < 8; nt++)
                mma16(O[nt], ap, bv_[nt]);
        }
    }

    float inv0 = 1.f / l0, inv1 = 1.f / l1;
    __half* y0 = g_y + ((size_t)b * TT + qg0) * CC + hh * HD;
    __half* y1 = g_y + ((size_t)b * TT + qg1) * CC + hh * HD;
    #pragma unroll
    for (int nt = 0; nt < 8; nt++) {
        int d = nt * 8 + 2 * t4;
        *(__half2*)&y0[d] = __floats2half2_rn(O[nt][0] * inv0, O[nt][1] * inv0);
        *(__half2*)&y1[d] = __floats2half2_rn(O[nt][2] * inv1, O[nt][3] * inv1);
    }
}

// ---------------------------------------------------------------------------
extern "C" void kernel_launch(void* const* d_in, const int* in_sizes, int n_in,
                              void* d_out, int out_size)
{
    const float* x  = (const float*)d_in[0];
    const float* h  = (const float*)d_in[1];
    const float* Wq = (const float*)d_in[2];
    const float* bq = (const float*)d_in[3];
    const float* Wk = (const float*)d_in[4];
    const float* bk = (const float*)d_in[5];
    const float* Wv = (const float*)d_in[6];
    const float* bv = (const float*)d_in[7];
    const float* Wp = (const float*)d_in[8];
    const float* bp = (const float*)d_in[9];
    float* out = (float*)d_out;

    const int gemm_smem = 73728;   // 2 stages * (A 18432B + B 18432B)
    static int smem_set = 0;
    if (!smem_set) {
        cudaFuncSetAttribute(qkv_gemm6, cudaFuncAttributeMaxDynamicSharedMemorySize,
                             gemm_smem);
        cudaFuncSetAttribute(proj_gemm6, cudaFuncAttributeMaxDynamicSharedMemorySize,
                             gemm_smem);
        smem_set = 1;
    }

    convert_fp16<<<8192, 256>>>(x, Wq, Wk, Wv, Wp);

    dim3 g1(24, 32);            // N=3072, M=4096 in 128x128 tiles
    qkv_gemm6<<<g1, 256, gemm_smem>>>(bq, bk, bv);

    dim3 g2(TT / 128, HH, BB);  // 16 x 16 x 2
    attn_tc6<<<g2, 256>>>(h);

    dim3 g3(8, 32);             // N=1024, M=4096
    proj_gemm6<<<g3, 256, gemm_smem>>>(bp, out);
}